// round 1
// baseline (speedup 1.0000x reference)
#include <cuda_runtime.h>
#include <cuda_bf16.h>

// Haar DWT2: input (8,32,512,512) f32 -> output (8,4,32,256,256) f32
// Subbands stacked axis=1: LL, LH, HL, HH
//   LL = (x00+x01+x10+x11)*0.5
//   LH = (x00+x01-x10-x11)*0.5   (pywt cH: highpass along H)
//   HL = (x00-x01+x10-x11)*0.5
//   HH = (x00-x01-x10+x11)*0.5
//
// Each thread: 4 output columns of one output row for one (b,c) plane.
// Loads: 2 input rows x 8 floats (2x float4 each) = 64B
// Stores: 4 subbands x float4 = 64B

#define H_IN  512
#define W_IN  512
#define H_OUT 256
#define W_OUT 256
#define C_DIM 32
#define B_DIM 8
#define COLS_PER_THREAD 4                 // output cols per thread
#define GROUPS_PER_ROW (W_OUT / COLS_PER_THREAD)   // 64

__global__ __launch_bounds__(256) void haar_dwt2_kernel(
    const float* __restrict__ in, float* __restrict__ out)
{
    // linear thread id over (bc, i, j4)
    unsigned t = blockIdx.x * blockDim.x + threadIdx.x;
    // total = B*C * H_OUT * GROUPS_PER_ROW = 8*32*256*64 = 4,194,304
    unsigned j4 = t & (GROUPS_PER_ROW - 1);          // 0..63
    unsigned i  = (t >> 6) & (H_OUT - 1);            // 0..255
    unsigned bc = t >> 14;                           // 0..255  (b*32 + c)

    // input base for this thread: plane bc, row 2*i, col 8*j4
    const float4* __restrict__ row0 = reinterpret_cast<const float4*>(
        in + ((size_t)bc * H_IN + 2u * i) * W_IN + 8u * j4);
    const float4* __restrict__ row1 = reinterpret_cast<const float4*>(
        in + ((size_t)bc * H_IN + 2u * i + 1u) * W_IN + 8u * j4);

    // front-batch all 4 loads (MLP=4)
    float4 a0 = row0[0];
    float4 a1 = row0[1];
    float4 b0 = row1[0];
    float4 b1 = row1[1];

    float r0[8] = {a0.x, a0.y, a0.z, a0.w, a1.x, a1.y, a1.z, a1.w};
    float r1[8] = {b0.x, b0.y, b0.z, b0.w, b1.x, b1.y, b1.z, b1.w};

    float ll[4], lh[4], hl[4], hh[4];
#pragma unroll
    for (int k = 0; k < 4; k++) {
        float x00 = r0[2*k], x01 = r0[2*k+1];
        float x10 = r1[2*k], x11 = r1[2*k+1];
        float s0 = x00 + x01, s1 = x10 + x11;   // row sums
        float d0 = x00 - x01, d1 = x10 - x11;   // row diffs
        ll[k] = (s0 + s1) * 0.5f;
        lh[k] = (s0 - s1) * 0.5f;
        hl[k] = (d0 + d1) * 0.5f;
        hh[k] = (d0 - d1) * 0.5f;
    }

    // output: [B, 4, C, 256, 256]
    unsigned b = bc >> 5;        // /32
    unsigned c = bc & 31;
    size_t plane = (size_t)H_OUT * W_OUT;                    // 65536
    size_t base  = (((size_t)b * 4) * C_DIM + c) * plane     // subband 0 for (b,c)
                 + (size_t)i * W_OUT + 4u * j4;
    size_t sub_stride = (size_t)C_DIM * plane;               // C*256*256

    float4* o = reinterpret_cast<float4*>(out + base);
    float4* oLH = reinterpret_cast<float4*>(out + base + sub_stride);
    float4* oHL = reinterpret_cast<float4*>(out + base + 2 * sub_stride);
    float4* oHH = reinterpret_cast<float4*>(out + base + 3 * sub_stride);

    *o   = make_float4(ll[0], ll[1], ll[2], ll[3]);
    *oLH = make_float4(lh[0], lh[1], lh[2], lh[3]);
    *oHL = make_float4(hl[0], hl[1], hl[2], hl[3]);
    *oHH = make_float4(hh[0], hh[1], hh[2], hh[3]);
}

extern "C" void kernel_launch(void* const* d_in, const int* in_sizes, int n_in,
                              void* d_out, int out_size)
{
    const float* in = (const float*)d_in[0];
    float* out = (float*)d_out;
    // total threads = 8*32*256*64 = 4,194,304
    unsigned total = B_DIM * C_DIM * H_OUT * GROUPS_PER_ROW;
    dim3 block(256);
    dim3 grid(total / 256);
    haar_dwt2_kernel<<<grid, block>>>(in, out);
}